// round 1
// baseline (speedup 1.0000x reference)
#include <cuda_runtime.h>

// Problem constants (shapes are fixed by the dataset)
#define BB 16
#define TT 96
#define TP1 97
#define HW 16384
#define NSTEP 6
#define MTHR 0.9f

// ---- scratch (device globals; no allocation APIs) ----
__device__ float         g_D[BB * HW * TT];      // d[b][p][t], t contiguous (~100MB)
__device__ double        g_delta[BB * TP1];      // delta per candidate (idx0 = empty, always 0)
__device__ unsigned char g_used[BB * TP1];
__device__ unsigned char g_topcov[BB * HW];
__device__ float         g_topval[BB * HW];
__device__ unsigned char g_newflag[BB * HW];
__device__ int           g_list[BB * HW];
__device__ int           g_cnt[BB];
__device__ int           g_cid[BB];

// ---------------------------------------------------------------------------
__global__ void k_init() {
    int i = blockIdx.x * blockDim.x + threadIdx.x;
    int n = gridDim.x * blockDim.x;
    for (int p = i; p < BB * HW; p += n) { g_topcov[p] = 0; g_newflag[p] = 0; }
    if (i < BB * TP1) { g_delta[i] = 0.0; g_used[i] = 0; }
    if (i < BB) { g_cnt[i] = 0; g_cid[i] = 0; }
}

// ---------------------------------------------------------------------------
// Precompute D[b][p][t] = cov ? (x - t*m)^2 - (x - bg)^2 : 0, and delta0[b][t].
// Block: 128 threads, handles one (b, 64-pixel tile). SMEM transpose gives
// coalesced reads (p-contiguous) AND coalesced writes (t-contiguous).
__global__ void k_precompute(const float* __restrict__ x,
                             const float* __restrict__ temps,
                             const float* __restrict__ msks,
                             const float* __restrict__ bg) {
    __shared__ float xs[64], eb[64];
    __shared__ float dsm[64][TP1];   // stride 97: conflict-free column reads

    const int b   = blockIdx.y;
    const int p0  = blockIdx.x * 64;
    const int tid = threadIdx.x;

    if (tid < 64) {
        float xv = x[b * HW + p0 + tid];
        float bv = bg[p0 + tid];
        xs[tid] = xv;
        float e = xv - bv;
        eb[tid] = e * e;
    }
    __syncthreads();

    const int half = tid >> 6;     // 0 or 1 -> two templates per iteration
    const int ps   = tid & 63;
    #pragma unroll 4
    for (int t2 = 0; t2 < TT; t2 += 2) {
        int t   = t2 + half;
        int idx = (b * TT + t) * HW + p0 + ps;
        float tv = temps[idx];
        float mv = msks[idx];
        float dd = 0.f;
        if (mv > MTHR) {
            float a = xs[ps] - tv * mv;
            dd = a * a - eb[ps];
        }
        dsm[ps][t] = dd;
    }
    __syncthreads();

    // write D: global index (b*HW + p0)*96 + i is fully contiguous in i
    const int obase = (b * HW + p0) * TT;
    for (int i = tid; i < 64 * TT; i += 128)
        g_D[obase + i] = dsm[i / TT][i % TT];

    // per-t partial sums -> delta0
    if (tid < TT) {
        float s = 0.f;
        #pragma unroll
        for (int p = 0; p < 64; p++) s += dsm[p][tid];
        atomicAdd(&g_delta[b * TP1 + 1 + tid], (double)s);
    }
}

// ---------------------------------------------------------------------------
// argmin over 97 candidates with used-penalty; first-index tie-break (jnp.argmin)
__global__ void k_argmin() {
    int b    = blockIdx.x;
    int lane = threadIdx.x;
    double bestv = 1e300;
    int    besti = TP1;
    for (int t = lane; t < TP1; t += 32) {
        double v = g_used[b * TP1 + t] ? 1e30 : g_delta[b * TP1 + t];
        if (v < bestv) { bestv = v; besti = t; }   // ascending t: keeps earliest on tie
    }
    for (int off = 16; off; off >>= 1) {
        double ov = __shfl_down_sync(0xffffffffu, bestv, off);
        int    oi = __shfl_down_sync(0xffffffffu, besti, off);
        if (ov < bestv || (ov == bestv && oi < besti)) { bestv = ov; besti = oi; }
    }
    if (lane == 0) {
        g_cid[b] = besti;
        if (besti != 0) g_used[b * TP1 + besti] = 1;
    }
}

// ---------------------------------------------------------------------------
// Paint selected template UNDER existing coverage; flag newly covered pixels.
__global__ void k_update(const float* __restrict__ temps,
                         const float* __restrict__ msks) {
    int b = blockIdx.y;
    int cid = g_cid[b];
    if (cid == 0) return;                 // empty template: no change
    int t = cid - 1;
    int p = blockIdx.x * blockDim.x + threadIdx.x;
    int idx = (b * TT + t) * HW + p;
    float mv = msks[idx];
    if (mv > MTHR) {
        int q = b * HW + p;
        if (!g_topcov[q]) {
            g_topval[q]  = temps[idx] * mv;
            g_topcov[q]  = 1;
            g_newflag[q] = 1;
        }
    }
}

// ---------------------------------------------------------------------------
// Deterministic compaction of new pixels into g_list (pixel order), clears flags.
__global__ void k_compact() {
    __shared__ int cnts[256];
    int b    = blockIdx.x;
    int tid  = threadIdx.x;
    int base = b * HW + tid * 64;

    int c = 0;
    #pragma unroll 8
    for (int j = 0; j < 64; j++) c += g_newflag[base + j];
    cnts[tid] = c;
    __syncthreads();
    // Hillis-Steele inclusive scan
    for (int off = 1; off < 256; off <<= 1) {
        int v = (tid >= off) ? cnts[tid - off] : 0;
        __syncthreads();
        cnts[tid] += v;
        __syncthreads();
    }
    int wr = cnts[tid] - c;               // exclusive prefix
    if (tid == 255) g_cnt[b] = cnts[255];
    for (int j = 0; j < 64; j++) {
        if (g_newflag[base + j]) { g_list[b * HW + wr++] = tid * 64 + j; }
        g_newflag[base + j] = 0;
    }
}

// ---------------------------------------------------------------------------
// delta[b][t] -= sum over new pixels of D[b][p][t]   (coalesced 384B rows)
__global__ void k_subtract() {
    __shared__ int sl[128];
    int b     = blockIdx.y;
    int cnt   = g_cnt[b];
    int start = blockIdx.x * 128;
    if (start >= cnt) return;
    int n   = min(128, cnt - start);
    int tid = threadIdx.x;
    if (tid < n) sl[tid] = g_list[b * HW + start + tid];
    __syncthreads();
    if (tid < TT) {
        double acc = 0.0;
        for (int j = 0; j < n; j++)
            acc += (double)g_D[(b * HW + sl[j]) * TT + tid];
        atomicAdd(&g_delta[b * TP1 + 1 + tid], -acc);
    }
}

// ---------------------------------------------------------------------------
__global__ void k_final(const float* __restrict__ bg, float* __restrict__ out) {
    int b = blockIdx.y;
    int p = blockIdx.x * blockDim.x + threadIdx.x;
    int q = b * HW + p;
    out[q] = g_topcov[q] ? g_topval[q] : bg[p];
}

// ---------------------------------------------------------------------------
extern "C" void kernel_launch(void* const* d_in, const int* in_sizes, int n_in,
                              void* d_out, int out_size) {
    const float* x      = (const float*)d_in[0];   // (16,1,128,128)
    const float* temps  = (const float*)d_in[1];   // (16,96,1,128,128)
    const float* msks   = (const float*)d_in[2];   // (16,96,1,128,128)
    const float* bg     = (const float*)d_in[3];   // (1,128,128)
    float* out = (float*)d_out;                    // (16,1,128,128)

    k_init<<<1024, 256>>>();
    k_precompute<<<dim3(HW / 64, BB), 128>>>(x, temps, msks, bg);

    for (int s = 0; s < NSTEP; s++) {
        k_argmin<<<BB, 32>>>();
        k_update<<<dim3(HW / 256, BB), 256>>>(temps, msks);
        k_compact<<<BB, 256>>>();
        k_subtract<<<dim3(HW / 128, BB), 128>>>();
    }
    k_final<<<dim3(HW / 256, BB), 256>>>(bg, out);
}

// round 2
// speedup vs baseline: 2.8140x; 2.8140x over previous
#include <cuda_runtime.h>

#define BB 16
#define TT 96
#define TP1 97
#define HW 16384
#define NSTEP 6
#define MTHR 0.9f

// ---- scratch (device globals; no allocation APIs) ----
__device__ float         g_D[(size_t)BB * HW * TT];  // d[b][p][t], t contiguous (~100MB)
__device__ double        g_delta[BB * TP1];          // idx0 = empty template, always 0
__device__ unsigned char g_used[BB * TP1];
__device__ unsigned char g_topcov[BB * HW];
__device__ float         g_topval[BB * HW];
__device__ int           g_cid[BB];

// ---------------------------------------------------------------------------
__global__ void k_init() {
    int i = threadIdx.x;
    for (int j = i; j < BB * TP1; j += 256) { g_delta[j] = 0.0; g_used[j] = 0; }
    if (i < BB) g_cid[i] = 0;
}

// ---------------------------------------------------------------------------
// Precompute D[b][p][t] = cov ? (x - t*m)^2 - (x - bg)^2 : 0, plus delta0[b][t].
// 256 threads handle a (b, 64-pixel) tile: 4 templates in flight per iteration.
// SMEM transpose gives coalesced reads (p-contig) AND coalesced writes (t-contig).
__global__ void k_precompute(const float* __restrict__ x,
                             const float* __restrict__ temps,
                             const float* __restrict__ msks,
                             const float* __restrict__ bg) {
    __shared__ float xs[64], eb[64];
    __shared__ float dsm[64][TP1];   // stride 97: conflict-free rows & columns

    const int b   = blockIdx.y;
    const int p0  = blockIdx.x * 64;
    const int tid = threadIdx.x;

    if (tid < 64) {
        float xv = x[b * HW + p0 + tid];
        float bv = bg[p0 + tid];
        xs[tid] = xv;
        float e = xv - bv;
        eb[tid] = e * e;
        g_topcov[b * HW + p0 + tid] = 0;   // fold init here
    }
    __syncthreads();

    const int ts = tid >> 6;     // 0..3 -> four templates per iteration
    const int ps = tid & 63;
    #pragma unroll 4
    for (int t4 = 0; t4 < TT; t4 += 4) {
        int t   = t4 + ts;
        int idx = (b * TT + t) * HW + p0 + ps;
        float tv = temps[idx];
        float mv = msks[idx];
        float dd = 0.f;
        if (mv > MTHR) {
            float a = xs[ps] - tv * mv;
            dd = a * a - eb[ps];
        }
        dsm[ps][t] = dd;
    }
    __syncthreads();

    // store D: global index (b*HW+p0)*96 + i fully contiguous in i
    const size_t obase = ((size_t)b * HW + p0) * TT;
    int r = tid / TT, c = tid % TT;        // one div at start, then incremental
    for (int i = tid; i < 64 * TT; i += 256) {
        g_D[obase + i] = dsm[r][c];
        c += 64; r += 2;                    // 256 = 2*96 + 64
        if (c >= TT) { c -= TT; r += 1; }
    }

    // per-t partial sums -> delta0
    if (tid < TT) {
        float s = 0.f;
        #pragma unroll
        for (int p = 0; p < 64; p++) s += dsm[p][tid];
        atomicAdd(&g_delta[b * TP1 + 1 + tid], (double)s);
    }
}

// ---------------------------------------------------------------------------
// argmin over 97 candidates with used-penalty; first-index tie-break (jnp.argmin)
__global__ void k_argmin() {
    int b    = blockIdx.x;
    int lane = threadIdx.x;
    double bestv = 1e300;
    int    besti = TP1;
    for (int t = lane; t < TP1; t += 32) {
        double v = g_used[b * TP1 + t] ? 1e30 : g_delta[b * TP1 + t];
        if (v < bestv) { bestv = v; besti = t; }   // ascending t: earliest on tie
    }
    for (int off = 16; off; off >>= 1) {
        double ov = __shfl_down_sync(0xffffffffu, bestv, off);
        int    oi = __shfl_down_sync(0xffffffffu, besti, off);
        if (ov < bestv || (ov == bestv && oi < besti)) { bestv = ov; besti = oi; }
    }
    if (lane == 0) {
        g_cid[b] = besti;
        if (besti != 0) g_used[b * TP1 + besti] = 1;
    }
}

// ---------------------------------------------------------------------------
// Fused paint + newly-covered detection + delta subtraction for one step.
// Block = 128 threads = 128 consecutive pixels of batch b.
__global__ void k_step(const float* __restrict__ temps,
                       const float* __restrict__ msks) {
    __shared__ unsigned wmask[4];

    const int b   = blockIdx.y;
    const int cid = g_cid[b];
    if (cid == 0) return;                  // empty template: nothing changes
    const int t   = cid - 1;
    const int tid = threadIdx.x;
    const int p0  = blockIdx.x * 128;
    const int q   = b * HW + p0 + tid;
    const int idx = (b * TT + t) * HW + p0 + tid;

    float mv = msks[idx];
    bool nw = false;
    if (mv > MTHR && !g_topcov[q]) {
        g_topval[q] = temps[idx] * mv;     // new object goes UNDER existing
        g_topcov[q] = 1;
        nw = true;
    }
    unsigned m = __ballot_sync(0xffffffffu, nw);
    if ((tid & 31) == 0) wmask[tid >> 5] = m;
    __syncthreads();

    if ((wmask[0] | wmask[1] | wmask[2] | wmask[3]) == 0u) return;

    // delta[b][t'] -= sum over newly covered pixels of D[b][p][t']
    if (tid < TT) {
        const float* Dp = g_D + ((size_t)b * HW + p0) * TT + tid;
        float a0 = 0.f, a1 = 0.f, a2 = 0.f, a3 = 0.f;
        #pragma unroll
        for (int w = 0; w < 4; w++) {
            unsigned mm = wmask[w];
            if (!mm) continue;
            const float* dp = Dp + (size_t)w * 32 * TT;
            #pragma unroll
            for (int j = 0; j < 32; j += 4) {
                if (mm & (1u <<  j     )) a0 += dp[(size_t)(j    ) * TT];
                if (mm & (1u << (j + 1))) a1 += dp[(size_t)(j + 1) * TT];
                if (mm & (1u << (j + 2))) a2 += dp[(size_t)(j + 2) * TT];
                if (mm & (1u << (j + 3))) a3 += dp[(size_t)(j + 3) * TT];
            }
        }
        float tot = (a0 + a1) + (a2 + a3);
        atomicAdd(&g_delta[b * TP1 + 1 + tid], -(double)tot);
    }
}

// ---------------------------------------------------------------------------
__global__ void k_final(const float* __restrict__ bg, float* __restrict__ out) {
    int b = blockIdx.y;
    int p = blockIdx.x * blockDim.x + threadIdx.x;
    int q = b * HW + p;
    out[q] = g_topcov[q] ? g_topval[q] : bg[p];
}

// ---------------------------------------------------------------------------
extern "C" void kernel_launch(void* const* d_in, const int* in_sizes, int n_in,
                              void* d_out, int out_size) {
    const float* x      = (const float*)d_in[0];   // (16,1,128,128)
    const float* temps  = (const float*)d_in[1];   // (16,96,1,128,128)
    const float* msks   = (const float*)d_in[2];   // (16,96,1,128,128)
    const float* bg     = (const float*)d_in[3];   // (1,128,128)
    float* out = (float*)d_out;                    // (16,1,128,128)

    k_init<<<1, 256>>>();
    k_precompute<<<dim3(HW / 64, BB), 256>>>(x, temps, msks, bg);

    for (int s = 0; s < NSTEP; s++) {
        k_argmin<<<BB, 32>>>();
        k_step<<<dim3(HW / 128, BB), 128>>>(temps, msks);
    }
    k_final<<<dim3(HW / 256, BB), 256>>>(bg, out);
}